// round 6
// baseline (speedup 1.0000x reference)
#include <cuda_runtime.h>
#include <cuda_fp16.h>
#include <cstdint>

// ---------------- problem constants ----------------
#define OUTF  11008
#define INF   4096
#define BATCH 64
#define NG    32            // 4096/128 quant groups
#define MTILE 128           // weight rows per CTA
#define KC    64            // K per chunk
#define NCHUNK 64           // 4096/64
#define NBLK  (OUTF / MTILE)   // 86 CTAs

// ---------------- i8 pipeline ----------------
#define NSLOT 8             // cp.async ring slots
#define SPREF 6             // prefetch distance

// ---- i8 smem layout (from 1KB-aligned base) ----
#define SC_OFF 0                          // 8KB scales
#define X_OFF  8192                       // 8 * 8KB
#define WR_OFF (X_OFF + NSLOT * 8192)
#define WF_OFF (WR_OFF + NSLOT * 8192)
#define SMEM_I8 (WF_OFF + 2 * 16384 + 1024)      // 173056

// ---------------- i32 pipeline ----------------
#define NSLOT4 4
#define SPREF4 3
#define WROW32 272                        // 256B row + 16B pad (conflict-free LDS128)
#define WSLOT32 (128 * WROW32)            // 34816
#define X4_OFF  8192
#define WR4_OFF (X4_OFF + NSLOT4 * 8192)          // 40960
#define WF4_OFF (WR4_OFF + NSLOT4 * WSLOT32)      // 180224
#define SMEM_I32 (WF4_OFF + 2 * 16384 + 1024)     // 214016

// ---------------- device globals ----------------
// NOTE: probe + dual-GEMM is a ROUND-TEMPORARY diagnostic structure. Once a
// bench passes and ncu shows which GEMM is live, the dead variant and the
// probe get deleted and modes hard-coded.
__device__ int g_w_mode;                  // 0 = int8, 1 = int32
__device__ int g_s_mode;                  // 0 = f16, 1 = bf16, 2 = f32
__device__ __half2 g_x16[BATCH * INF / 2];
__device__ __half  g_sc16[OUTF * NG];
__device__ float   g_badd[OUTF];

// ---------------- helpers ----------------
static __device__ __forceinline__ uint32_t smem_u32(const void* p) {
    uint32_t a;
    asm("{ .reg .u64 t; cvta.to.shared.u64 t, %1; cvt.u32.u64 %0, t; }" : "=r"(a) : "l"(p));
    return a;
}
static __device__ __forceinline__ uint32_t swz(uint32_t off) {
    return off ^ ((off >> 3) & 0x70);     // SW128 for 128B rows
}
static __device__ __forceinline__ void cpa16(uint32_t dst, const void* src) {
    asm volatile("cp.async.cg.shared.global [%0], [%1], 16;" :: "r"(dst), "l"(src));
}
static __device__ __forceinline__ void cpa_commit() {
    asm volatile("cp.async.commit_group;" ::: "memory");
}
static __device__ __forceinline__ void ldsm4(uint32_t* r, uint32_t addr) {
    asm volatile("ldmatrix.sync.aligned.m8n8.x4.shared.b16 {%0,%1,%2,%3}, [%4];"
        : "=r"(r[0]), "=r"(r[1]), "=r"(r[2]), "=r"(r[3]) : "r"(addr));
}
static __device__ __forceinline__ void mma16816(float* d, const uint32_t* a,
                                                uint32_t b0, uint32_t b1) {
    asm volatile("mma.sync.aligned.m16n8k16.row.col.f32.f16.f16.f32 "
        "{%0,%1,%2,%3}, {%4,%5,%6,%7}, {%8,%9}, {%0,%1,%2,%3};"
        : "+f"(d[0]), "+f"(d[1]), "+f"(d[2]), "+f"(d[3])
        : "r"(a[0]), "r"(a[1]), "r"(a[2]), "r"(a[3]), "r"(b0), "r"(b1));
}
static __device__ __forceinline__ __half2 u32_as_h2(uint32_t u) {
    __half2 h; *reinterpret_cast<uint32_t*>(&h) = u; return h;
}
static __device__ __forceinline__ uint32_t h2_as_u32(__half2 h) {
    return *reinterpret_cast<uint32_t*>(&h);
}

#define LDS128(r0, r1, r2, r3, addr) \
    asm volatile("ld.shared.v4.u32 {%0, %1, %2, %3}, [%4];" \
        : "=r"(r0), "=r"(r1), "=r"(r2), "=r"(r3) : "r"(addr))
#define STS128(addr, r0, r1, r2, r3) \
    asm volatile("st.shared.v4.b32 [%0], {%1, %2, %3, %4};" \
        :: "r"(addr), "r"(r0), "r"(r1), "r"(r2), "r"(r3) : "memory")

// convert 4 int8 bytes (packed) to 2 half2, times s2
static __device__ __forceinline__ void dq4(uint32_t packed, __half2 s2, __half2 c1152,
                                           uint32_t& o0, uint32_t& o1) {
    uint32_t v  = packed ^ 0x80808080u;
    uint32_t lo = __byte_perm(v, 0x64646464u, 0x4140);
    uint32_t hi = __byte_perm(v, 0x64646464u, 0x4342);
    o0 = h2_as_u32(__hmul2(__hsub2(u32_as_h2(lo), c1152), s2));
    o1 = h2_as_u32(__hmul2(__hsub2(u32_as_h2(hi), c1152), s2));
}

// ---------------- probe: classify input dtypes on device ----------------
__global__ void probe_kernel(const unsigned* __restrict__ w,
                             const unsigned* __restrict__ s) {
    bool bf = true, fh = true, i32 = true;
    for (int i = 0; i < 64; i++) {
        unsigned v = s[i];
        #pragma unroll
        for (int h = 0; h < 2; h++) {
            unsigned u = (h ? (v >> 16) : v) & 0xFFFFu;
            float ab = __uint_as_float(u << 16);
            float af = __half2float(__ushort_as_half((unsigned short)u));
            bf &= (ab > 5e-5f && ab < 0.02f);
            fh &= (af > 5e-5f && af < 0.02f);
        }
        int q = (int)w[i];
        i32 &= (q >= -127 && q <= 127);
    }
    g_s_mode = bf ? 1 : (fh ? 0 : 2);
    g_w_mode = i32 ? 1 : 0;
}

// ---------------- canonicalize x / scale / bias+residual ----------------
__global__ void cvt_x_kernel(const float* __restrict__ x) {
    int i = blockIdx.x * blockDim.x + threadIdx.x;
    float2 v = reinterpret_cast<const float2*>(x)[i];
    g_x16[i] = __floats2half2_rn(v.x, v.y);
}

static __device__ __forceinline__ float read_mode16(const void* p, int i, int mode) {
    if (mode == 1) {
        unsigned short u = reinterpret_cast<const unsigned short*>(p)[i];
        return __uint_as_float(((unsigned)u) << 16);
    } else if (mode == 0) {
        return __half2float(reinterpret_cast<const __half*>(p)[i]);
    }
    return reinterpret_cast<const float*>(p)[i];
}

__global__ void cvt_scale_kernel(const void* __restrict__ s) {
    int i = blockIdx.x * blockDim.x + threadIdx.x;   // OUTF*NG
    g_sc16[i] = __float2half(read_mode16(s, i, g_s_mode));
}
__global__ void cvt_badd_kernel(const void* __restrict__ b, const void* __restrict__ r) {
    int i = blockIdx.x * blockDim.x + threadIdx.x;   // OUTF (43*256)
    int m = g_s_mode;
    g_badd[i] = read_mode16(b, i, m) + read_mode16(r, i, m);
}

// ================= GEMM (int8 weights) =================
__global__ void __launch_bounds__(256, 1)
gemm_i8(const int8_t* __restrict__ W, float* __restrict__ out) {
    if (g_w_mode != 0) return;
    extern __shared__ char smem_raw[];
    uint32_t sb = (smem_u32(smem_raw) + 1023) & ~1023u;

    const int tid = threadIdx.x, lane = tid & 31, wid = tid >> 5;
    const int mr = wid & 3, nc = wid >> 2;
    const int row0 = blockIdx.x * MTILE;
    const char* xb = reinterpret_cast<const char*>(g_x16);

    auto issue_chunk = [&](int p) {
        const int slot = p & (NSLOT - 1);
        const uint32_t wsl = sb + WR_OFF + slot * 8192;
        const uint32_t xsl = sb + X_OFF + slot * 8192;
        const int k0 = p * KC;
        #pragma unroll
        for (int j = 0; j < 2; j++) {
            int c = tid + j * 256, r = c >> 2, q = c & 3;
            cpa16(wsl + c * 16, W + (size_t)(row0 + r) * INF + k0 + q * 16);
        }
        #pragma unroll
        for (int j = 0; j < 2; j++) {
            int c = tid + j * 256, r = c >> 3, q = c & 7;
            cpa16(xsl + swz(r * 128 + q * 16),
                  xb + (size_t)r * (INF * 2) + (size_t)k0 * 2 + q * 16);
        }
    };

    {
        const char* scb = reinterpret_cast<const char*>(g_sc16) + (size_t)row0 * NG * 2;
        #pragma unroll
        for (int j = 0; j < 2; j++) {
            int c = tid + j * 256;
            cpa16(sb + SC_OFF + c * 16, scb + c * 16);
        }
        issue_chunk(0);
        cpa_commit();
        for (int p = 1; p < SPREF; p++) { issue_chunk(p); cpa_commit(); }
    }

    const __half2 c1152 = __half2half2(__ushort_as_half((unsigned short)0x6480));
    float acc[2][4][4] = {};

    for (int i = 0; i < NCHUNK; i++) {
        asm volatile("cp.async.wait_group %0;" :: "n"(SPREF - 1) : "memory");
        __syncthreads();

        const int slot = i & (NSLOT - 1);
        const uint32_t wsl = sb + WR_OFF + slot * 8192;
        const uint32_t xsl = sb + X_OFF + slot * 8192;
        const uint32_t wfp = sb + WF_OFF + (i & 1) * 16384;

        uint32_t bfr[4][8];
        const int t = lane >> 3;
        #pragma unroll
        for (int kt = 0; kt < 4; kt++)
            #pragma unroll
            for (int np = 0; np < 2; np++) {
                int n  = nc * 32 + np * 16 + ((t >> 1) << 3) + (lane & 7);
                int cb = kt * 32 + ((t & 1) << 4);
                ldsm4(&bfr[kt][np * 4], xsl + swz(n * 128 + cb));
            }

        const int g = i >> 1;
        #pragma unroll
        for (int j = 0; j < 2; j++) {
            int c = tid + j * 256, r = c >> 2, q = c & 3;
            uint32_t w0, w1, w2, w3;
            LDS128(w0, w1, w2, w3, wsl + c * 16);
            unsigned short sv;
            asm volatile("ld.shared.u16 %0, [%1];" : "=h"(sv)
                : "r"(sb + SC_OFF + (uint32_t)(r * NG + g) * 2) : "memory");
            __half2 s2 = __half2half2(__ushort_as_half(sv));
            uint32_t wv[4] = {w0, w1, w2, w3};
            uint32_t o[8];
            #pragma unroll
            for (int k = 0; k < 4; k++) dq4(wv[k], s2, c1152, o[2*k], o[2*k+1]);
            uint32_t off = (uint32_t)r * 128 + (uint32_t)q * 32;
            STS128(wfp + swz(off),      o[0], o[1], o[2], o[3]);
            STS128(wfp + swz(off + 16), o[4], o[5], o[6], o[7]);
        }

        if (i + SPREF < NCHUNK) issue_chunk(i + SPREF);
        cpa_commit();
        __syncthreads();

        #pragma unroll
        for (int kt = 0; kt < 4; kt++)
            #pragma unroll
            for (int mt = 0; mt < 2; mt++) {
                uint32_t afr[4];
                int row = mr * 32 + mt * 16 + ((t & 1) << 3) + (lane & 7);
                int cb  = kt * 32 + ((t >> 1) << 4);
                ldsm4(afr, wfp + swz(row * 128 + cb));
                #pragma unroll
                for (int nt = 0; nt < 4; nt++)
                    mma16816(acc[mt][nt], afr, bfr[kt][nt * 2], bfr[kt][nt * 2 + 1]);
            }
    }

    const int olo = row0 + mr * 32 + (lane >> 2);
    #pragma unroll
    for (int mt = 0; mt < 2; mt++) {
        int o0 = olo + mt * 16;
        float b0 = g_badd[o0], b8 = g_badd[o0 + 8];
        #pragma unroll
        for (int nt = 0; nt < 4; nt++) {
            int bc = nc * 32 + nt * 8 + (lane & 3) * 2;
            out[(size_t)bc * OUTF + o0]           = acc[mt][nt][0] + b0;
            out[(size_t)(bc + 1) * OUTF + o0]     = acc[mt][nt][1] + b0;
            out[(size_t)bc * OUTF + o0 + 8]       = acc[mt][nt][2] + b8;
            out[(size_t)(bc + 1) * OUTF + o0 + 8] = acc[mt][nt][3] + b8;
        }
    }
}

// ================= GEMM (int32 weights) =================
__global__ void __launch_bounds__(256, 1)
gemm_i32(const int* __restrict__ W, float* __restrict__ out) {
    if (g_w_mode != 1) return;
    extern __shared__ char smem_raw[];
    uint32_t sb = (smem_u32(smem_raw) + 1023) & ~1023u;

    const int tid = threadIdx.x, lane = tid & 31, wid = tid >> 5;
    const int mr = wid & 3, nc = wid >> 2;
    const int row0 = blockIdx.x * MTILE;
    const char* xb = reinterpret_cast<const char*>(g_x16);

    auto issue_chunk = [&](int p) {
        const int slot = p & (NSLOT4 - 1);
        const uint32_t wsl = sb + WR4_OFF + slot * WSLOT32;
        const uint32_t xsl = sb + X4_OFF + slot * 8192;
        const int k0 = p * KC;
        #pragma unroll
        for (int j = 0; j < 8; j++) {        // 2048 x 16B = 32KB int32 W
            int c = tid + j * 256, r = c >> 4, q = c & 15;
            cpa16(wsl + r * WROW32 + q * 16,
                  W + (size_t)(row0 + r) * INF + k0 + q * 4);
        }
        #pragma unroll
        for (int j = 0; j < 2; j++) {
            int c = tid + j * 256, r = c >> 3, q = c & 7;
            cpa16(xsl + swz(r * 128 + q * 16),
                  xb + (size_t)r * (INF * 2) + (size_t)k0 * 2 + q * 16);
        }
    };

    {
        const char* scb = reinterpret_cast<const char*>(g_sc16) + (size_t)row0 * NG * 2;
        #pragma unroll
        for (int j = 0; j < 2; j++) {
            int c = tid + j * 256;
            cpa16(sb + SC_OFF + c * 16, scb + c * 16);
        }
        issue_chunk(0);
        cpa_commit();
        for (int p = 1; p < SPREF4; p++) { issue_chunk(p); cpa_commit(); }
    }

    const __half2 c1152 = __half2half2(__ushort_as_half((unsigned short)0x6480));
    float acc[2][4][4] = {};

    for (int i = 0; i < NCHUNK; i++) {
        asm volatile("cp.async.wait_group %0;" :: "n"(SPREF4 - 1) : "memory");
        __syncthreads();

        const int slot = i & (NSLOT4 - 1);
        const uint32_t wsl = sb + WR4_OFF + slot * WSLOT32;
        const uint32_t xsl = sb + X4_OFF + slot * 8192;
        const uint32_t wfp = sb + WF4_OFF + (i & 1) * 16384;

        uint32_t bfr[4][8];
        const int t = lane >> 3;
        #pragma unroll
        for (int kt = 0; kt < 4; kt++)
            #pragma unroll
            for (int np = 0; np < 2; np++) {
                int n  = nc * 32 + np * 16 + ((t >> 1) << 3) + (lane & 7);
                int cb = kt * 32 + ((t & 1) << 4);
                ldsm4(&bfr[kt][np * 4], xsl + swz(n * 128 + cb));
            }

        // dequant: thread owns row r = tid&127, half h = tid>>7
        const int g = i >> 1;
        {
            const int r = tid & 127, h = tid >> 7;
            unsigned short sv;
            asm volatile("ld.shared.u16 %0, [%1];" : "=h"(sv)
                : "r"(sb + SC_OFF + (uint32_t)(r * NG + g) * 2) : "memory");
            __half2 s2 = __half2half2(__ushort_as_half(sv));
            uint32_t o[16];
            #pragma unroll
            for (int k = 0; k < 8; k++) {
                uint32_t w0, w1, w2, w3;
                LDS128(w0, w1, w2, w3, wsl + r * WROW32 + h * 128 + k * 16);
                uint32_t t01 = __byte_perm(w0, w1, 0x0040);
                uint32_t t23 = __byte_perm(w2, w3, 0x0040);
                uint32_t packed = __byte_perm(t01, t23, 0x5410);
                dq4(packed, s2, c1152, o[2*k], o[2*k+1]);
            }
            uint32_t off = (uint32_t)r * 128 + (uint32_t)h * 64;
            STS128(wfp + swz(off),      o[0],  o[1],  o[2],  o[3]);
            STS128(wfp + swz(off + 16), o[4],  o[5],  o[6],  o[7]);
            STS128(wfp + swz(off + 32), o[8],  o[9],  o[10], o[11]);
            STS128(wfp + swz(off + 48), o[12], o[13], o[14], o[15]);
        }

        if (i + SPREF4 < NCHUNK) issue_chunk(i + SPREF4);
        cpa_commit();
        __syncthreads();

        #pragma unroll
        for (int kt = 0; kt < 4; kt++)
            #pragma unroll
            for (int mt = 0; mt < 2; mt++) {
                uint32_t afr[4];
                int row = mr * 32 + mt * 16 + ((t & 1) << 3) + (lane & 7);
                int cb  = kt * 32 + ((t >> 1) << 4);
                ldsm4(afr, wfp + swz(row * 128 + cb));
                #pragma unroll
                for (int nt = 0; nt < 4; nt++)
                    mma16816(acc[mt][nt], afr, bfr[kt][nt * 2], bfr[kt][nt * 2 + 1]);
            }
    }

    const int olo = row0 + mr * 32 + (lane >> 2);
    #pragma unroll
    for (int mt = 0; mt < 2; mt++) {
        int o0 = olo + mt * 16;
        float b0 = g_badd[o0], b8 = g_badd[o0 + 8];
        #pragma unroll
        for (int nt = 0; nt < 4; nt++) {
            int bc = nc * 32 + nt * 8 + (lane & 3) * 2;
            out[(size_t)bc * OUTF + o0]           = acc[mt][nt][0] + b0;
            out[(size_t)(bc + 1) * OUTF + o0]     = acc[mt][nt][1] + b0;
            out[(size_t)bc * OUTF + o0 + 8]       = acc[mt][nt][2] + b8;
            out[(size_t)(bc + 1) * OUTF + o0 + 8] = acc[mt][nt][3] + b8;
        }
    }
}

// ---------------- launch ----------------
extern "C" void kernel_launch(void* const* d_in, const int* in_sizes, int n_in,
                              void* d_out, int out_size) {
    const void* x = nullptr; const void* wq = nullptr; const void* scale = nullptr;
    const void* bias = nullptr; const void* wres = nullptr;
    for (int i = 0; i < n_in; i++) {
        long long n = in_sizes[i];
        if (n == (long long)BATCH * INF)     x = d_in[i];
        else if (n == (long long)OUTF * INF) wq = d_in[i];
        else if (n == (long long)OUTF * NG)  scale = d_in[i];
        else if (n == OUTF) { if (!bias) bias = d_in[i]; else wres = d_in[i]; }
    }
    // Fallback: if size-matching failed (unexpected manifest), use positional order
    // so we never launch with null pointers.
    if (!x || !wq || !scale || !bias || !wres) {
        if (n_in >= 5) {
            x = d_in[0]; wq = d_in[1]; scale = d_in[2]; bias = d_in[3]; wres = d_in[4];
        } else {
            return;  // refuse to launch on malformed input
        }
    }
    float* out = (float*)d_out;

    probe_kernel<<<1, 1>>>((const unsigned*)wq, (const unsigned*)scale);
    cvt_x_kernel<<<(BATCH * INF / 2) / 256, 256>>>((const float*)x);
    cvt_scale_kernel<<<(OUTF * NG) / 256, 256>>>(scale);
    cvt_badd_kernel<<<OUTF / 256, 256>>>(bias, wres);

    (void)cudaFuncSetAttribute(gemm_i8,  cudaFuncAttributeMaxDynamicSharedMemorySize, SMEM_I8);
    (void)cudaFuncSetAttribute(gemm_i32, cudaFuncAttributeMaxDynamicSharedMemorySize, SMEM_I32);
    gemm_i8<<<NBLK, 256, SMEM_I8>>>((const int8_t*)wq, out);
    gemm_i32<<<NBLK, 256, SMEM_I32>>>((const int*)wq, out);
}